// round 2
// baseline (speedup 1.0000x reference)
#include <cuda_runtime.h>
#include <cstdint>

#define BATCH 256
#define TSEQ  512
#define HID   512
#define FUT   64
#define NCTA  128
#define NTHR  256
#define MB    64      // batch rows per CTA tile
#define UH    16      // hidden units per CTA slice
#define KC    64      // K chunk for weight staging
#define NCHUNK (HID / KC)   // 8
#define HPITCH 516          // padded row pitch (floats) for h tile in smem
#define WPITCH 68           // padded row pitch (floats) for w chunk in smem
#define WBUFSZ (64 * WPITCH)

#define SMEM_BYTES ((MB * HPITCH + 2 * WBUFSZ) * 4)   // 166,912 B

// ---------------- persistent device state ----------------
__device__ float g_h0[2][BATCH * HID];
__device__ float g_h1[2][BATCH * HID];
__device__ float g_c0[BATCH * HID];
__device__ float g_c1[BATCH * HID];
__device__ float g_o[BATCH];
__device__ unsigned g_arrive;
__device__ unsigned g_release;

// ---------------- helpers ----------------
__device__ __forceinline__ void cp16(float* dst_smem, const float* src_gmem) {
    unsigned d = (unsigned)__cvta_generic_to_shared(dst_smem);
    asm volatile("cp.async.cg.shared.global [%0], [%1], 16;" :: "r"(d), "l"(src_gmem));
}
__device__ __forceinline__ void cp_commit() { asm volatile("cp.async.commit_group;"); }

__device__ __forceinline__ float sgm(float x) { return 1.0f / (1.0f + expf(-x)); }

// grid-wide barrier: monotonic counters, reset by init kernel each launch
__device__ __forceinline__ void gbar(unsigned& gen) {
    gen++;
    __syncthreads();
    if (threadIdx.x == 0) {
        __threadfence();
        unsigned a = atomicAdd(&g_arrive, 1u) + 1u;
        if (a == (unsigned)NCTA * gen) {
            atomicExch(&g_release, gen);
        } else {
            while (*((volatile unsigned*)&g_release) < gen) { __nanosleep(32); }
        }
        __threadfence();
    }
    __syncthreads();
}

// stage h tile [MB x HID] (fp32) from global (L2, .cg) into padded smem
__device__ __forceinline__ void stage_h(float* shh, const float* hsrc, int tid) {
#pragma unroll
    for (int i = 0; i < 32; i++) {
        int f4 = tid + i * NTHR;        // 0..8191, 128 float4 per row
        int r  = f4 >> 7;
        int c  = f4 & 127;
        cp16(shh + r * HPITCH + c * 4, hsrc + (size_t)r * HID + c * 4);
    }
}

// stage weight chunk: 64 gate rows (4 gates x 16 units of this slice) x KC cols
__device__ __forceinline__ void stage_w(float* shwbuf, const float* Wbase, int u0, int chunk, int tid) {
    int kc0 = chunk * KC;
#pragma unroll
    for (int i = 0; i < 4; i++) {
        int f4 = tid + i * NTHR;        // 0..1023, 16 float4 per row
        int r  = f4 >> 4;
        int kq = f4 & 15;
        int q  = r >> 4, jj = r & 15;
        cp16(shwbuf + r * WPITCH + kq * 4,
             Wbase + (size_t)(q * HID + u0 + jj) * HID + kc0 + kq * 4);
    }
}

__device__ __forceinline__ void compute_chunk(float acc[4][4], const float* shh, const float* wb,
                                              int kbase, int j, int bloc) {
#pragma unroll 8
    for (int kk = 0; kk < KC; kk += 4) {
        float4 hv[4];
#pragma unroll
        for (int ib = 0; ib < 4; ib++)
            hv[ib] = *(const float4*)(shh + (bloc + ib) * HPITCH + kbase + kk);
        float4 wv[4];
#pragma unroll
        for (int q = 0; q < 4; q++)
            wv[q] = *(const float4*)(wb + (q * UH + j) * WPITCH + kk);
#pragma unroll
        for (int q = 0; q < 4; q++) {
#pragma unroll
            for (int ib = 0; ib < 4; ib++) {
                acc[q][ib] = fmaf(wv[q].x, hv[ib].x, acc[q][ib]);
                acc[q][ib] = fmaf(wv[q].y, hv[ib].y, acc[q][ib]);
                acc[q][ib] = fmaf(wv[q].z, hv[ib].z, acc[q][ib]);
                acc[q][ib] = fmaf(wv[q].w, hv[ib].w, acc[q][ib]);
            }
        }
    }
}

// one K=512 GEMM pass: gates[64b x 64rows] += h_tile @ W_rows^T
__device__ __forceinline__ void gemm_pass(float acc[4][4], const float* Wbase, const float* hsrc,
                                          float* shh, float* shw, int u0, int tid, int j, int bloc) {
    stage_h(shh, hsrc, tid);
    stage_w(shw, Wbase, u0, 0, tid);
    cp_commit();
    stage_w(shw + WBUFSZ, Wbase, u0, 1, tid);
    cp_commit();
#pragma unroll 1
    for (int c = 0; c < NCHUNK; c++) {
        if (c < NCHUNK - 1) asm volatile("cp.async.wait_group 1;");
        else                asm volatile("cp.async.wait_group 0;");
        __syncthreads();
        compute_chunk(acc, shh, shw + (c & 1) * WBUFSZ, c * KC, j, bloc);
        __syncthreads();
        if (c + 2 < NCHUNK) {
            stage_w(shw + (c & 1) * WBUFSZ, Wbase, u0, c + 2, tid);
            cp_commit();
        }
    }
}

// LSTM elementwise update for this thread's unit (4 batch rows)
__device__ __forceinline__ void cell_update(const float acc[4][4], const float bs[4],
                                            const float* xinv, const float xw[4],
                                            float* cbuf, float* hout,
                                            int b0, int bloc, int ju) {
#pragma unroll
    for (int ib = 0; ib < 4; ib++) {
        int b = b0 + bloc + ib;
        float xin = xinv ? xinv[ib] : 0.0f;
        float pi = acc[0][ib] + bs[0] + xin * xw[0];
        float pf = acc[1][ib] + bs[1] + xin * xw[1];
        float pg = acc[2][ib] + bs[2] + xin * xw[2];
        float po = acc[3][ib] + bs[3] + xin * xw[3];
        size_t idx = (size_t)b * HID + ju;
        float c = sgm(pf) * cbuf[idx] + sgm(pi) * tanhf(pg);
        cbuf[idx] = c;
        __stcg(hout + idx, sgm(po) * tanhf(c));
    }
}

// out[:, s] = hbuf @ wvec + bias ; also stashes to g_o
__device__ __forceinline__ void head_dot(const float* hbuf, const float* wvec, const float* bias,
                                         float* out, int s, int b0, int tid) {
    int warp = tid >> 5, lane = tid & 31;
    float bv = __ldg(bias);
    for (int bb = warp; bb < MB; bb += 8) {
        int b = b0 + bb;
        const float4* hp  = (const float4*)(hbuf + (size_t)b * HID);
        const float4* wp4 = (const float4*)wvec;
        float s4 = 0.0f;
#pragma unroll
        for (int rr = 0; rr < 4; rr++) {
            float4 hv = __ldcg(hp + rr * 32 + lane);
            float4 wv = __ldg(wp4 + rr * 32 + lane);
            s4 += hv.x * wv.x + hv.y * wv.y + hv.z * wv.z + hv.w * wv.w;
        }
#pragma unroll
        for (int off = 16; off; off >>= 1) s4 += __shfl_xor_sync(0xffffffffu, s4, off);
        if (lane == 0) {
            float o = s4 + bv;
            out[b * FUT + s] = o;
            g_o[b] = o;
        }
    }
}

__device__ __forceinline__ void zero_acc(float acc[4][4]) {
#pragma unroll
    for (int q = 0; q < 4; q++)
#pragma unroll
        for (int ib = 0; ib < 4; ib++) acc[q][ib] = 0.0f;
}

// ---------------- kernels ----------------
__global__ void init_kernel() {
    size_t n = (size_t)BATCH * HID;
    size_t i = blockIdx.x * (size_t)blockDim.x + threadIdx.x;
    size_t stride = (size_t)gridDim.x * blockDim.x;
    for (size_t k = i; k < n; k += stride) {
        g_h0[0][k] = 0.f; g_h0[1][k] = 0.f;
        g_h1[0][k] = 0.f; g_h1[1][k] = 0.f;
        g_c0[k] = 0.f;    g_c1[k] = 0.f;
    }
    if (i == 0) { g_arrive = 0u; g_release = 0u; }
}

__global__ void __launch_bounds__(NTHR, 1)
lstm_kernel(const float* __restrict__ x,
            const float* __restrict__ w_ih0, const float* __restrict__ w_hh0,
            const float* __restrict__ b_ih0, const float* __restrict__ b_hh0,
            const float* __restrict__ w_ih1, const float* __restrict__ w_hh1,
            const float* __restrict__ b_ih1, const float* __restrict__ b_hh1,
            const float* __restrict__ fc_w,  const float* __restrict__ fc_b,
            const float* __restrict__ pw_ih0, const float* __restrict__ pw_hh0,
            const float* __restrict__ pb_ih0, const float* __restrict__ pb_hh0,
            const float* __restrict__ pw_ih1, const float* __restrict__ pw_hh1,
            const float* __restrict__ pb_ih1, const float* __restrict__ pb_hh1,
            const float* __restrict__ pfc_w,  const float* __restrict__ pfc_b,
            float* __restrict__ out) {
    extern __shared__ float smem[];
    float* shh = smem;                      // MB x HPITCH
    float* shw = smem + MB * HPITCH;        // 2 x WBUFSZ

    const int tid  = threadIdx.x;
    const int bt   = blockIdx.x & 3;        // 4 batch tiles
    const int sl   = blockIdx.x >> 2;       // 32 hidden slices
    const int b0   = bt * MB;
    const int u0   = sl * UH;
    const int warp = tid >> 5, lane = tid & 31;
    const int j    = ((warp & 1) << 3) | (lane >> 2);  // unit-in-slice 0..15
    const int bg   = ((warp >> 1) << 2) | (lane & 3);  // batch group 0..15
    const int bloc = bg << 2;
    const int ju   = u0 + j;

    // hoist per-thread biases / scalar-input weight columns (constant over all steps)
    float bs0[4], bs1[4], pbs0[4], pbs1[4], wi0[4], pwi0[4];
#pragma unroll
    for (int q = 0; q < 4; q++) {
        int r = q * HID + ju;
        bs0[q]  = __ldg(b_ih0 + r)  + __ldg(b_hh0 + r);
        bs1[q]  = __ldg(b_ih1 + r)  + __ldg(b_hh1 + r);
        pbs0[q] = __ldg(pb_ih0 + r) + __ldg(pb_hh0 + r);
        pbs1[q] = __ldg(pb_ih1 + r) + __ldg(pb_hh1 + r);
        wi0[q]  = __ldg(w_ih0 + r);
        pwi0[q] = __ldg(pw_ih0 + r);
    }

    unsigned gen = 0;
    int p = 0;
    float acc[4][4];

    // ---------------- warmup over observed sequence ----------------
    for (int t = 0; t < TSEQ; t++) {
        gbar(gen);                                   // h0[p] from prev step visible
        // layer 0: gates = h0[p] @ w_hh0^T (+ x_t * w_ih0 + biases)
        zero_acc(acc);
        gemm_pass(acc, w_hh0, g_h0[p] + (size_t)b0 * HID, shh, shw, u0, tid, j, bloc);
        {
            float xin[4];
#pragma unroll
            for (int ib = 0; ib < 4; ib++)
                xin[ib] = __ldg(x + (size_t)(b0 + bloc + ib) * TSEQ + t);
            cell_update(acc, bs0, xin, wi0, g_c0, g_h0[p ^ 1], b0, bloc, ju);
        }
        gbar(gen);                                   // h0[p^1] complete
        // layer 1: gates = h0_new @ w_ih1^T + h1[p] @ w_hh1^T + biases
        zero_acc(acc);
        gemm_pass(acc, w_ih1, g_h0[p ^ 1] + (size_t)b0 * HID, shh, shw, u0, tid, j, bloc);
        gemm_pass(acc, w_hh1, g_h1[p]     + (size_t)b0 * HID, shh, shw, u0, tid, j, bloc);
        cell_update(acc, bs1, (const float*)0, bs1 /*unused*/, g_c1, g_h1[p ^ 1], b0, bloc, ju);
        p ^= 1;
    }

    // out[:, 0] = fc(h1_final); also seeds g_o
    gbar(gen);
    if (sl == 0) head_dot(g_h1[p], fc_w, fc_b, out, 0, b0, tid);

    // ---------------- autoregressive prediction ----------------
    for (int s = 1; s < FUT; s++) {
        gbar(gen);                                   // g_o ready
        // pred layer 0
        zero_acc(acc);
        gemm_pass(acc, pw_hh0, g_h0[p] + (size_t)b0 * HID, shh, shw, u0, tid, j, bloc);
        {
            float xin[4];
#pragma unroll
            for (int ib = 0; ib < 4; ib++)
                xin[ib] = __ldcg(&g_o[b0 + bloc + ib]);
            cell_update(acc, pbs0, xin, pwi0, g_c0, g_h0[p ^ 1], b0, bloc, ju);
        }
        gbar(gen);
        // pred layer 1
        zero_acc(acc);
        gemm_pass(acc, pw_ih1, g_h0[p ^ 1] + (size_t)b0 * HID, shh, shw, u0, tid, j, bloc);
        gemm_pass(acc, pw_hh1, g_h1[p]     + (size_t)b0 * HID, shh, shw, u0, tid, j, bloc);
        cell_update(acc, pbs1, (const float*)0, pbs1 /*unused*/, g_c1, g_h1[p ^ 1], b0, bloc, ju);
        gbar(gen);
        if (sl == 0) head_dot(g_h1[p ^ 1], pfc_w, pfc_b, out, s, b0, tid);
        p ^= 1;
    }
}

// ---------------- launch ----------------
extern "C" void kernel_launch(void* const* d_in, const int* in_sizes, int n_in,
                              void* d_out, int out_size) {
    (void)in_sizes; (void)n_in; (void)out_size;
    cudaFuncSetAttribute(lstm_kernel, cudaFuncAttributeMaxDynamicSharedMemorySize, SMEM_BYTES);

    const float* x      = (const float*)d_in[0];
    // d_in[1] = future (int scalar) — shapes are fixed, FUT hardcoded
    const float* w_ih0  = (const float*)d_in[2];
    const float* w_hh0  = (const float*)d_in[3];
    const float* b_ih0  = (const float*)d_in[4];
    const float* b_hh0  = (const float*)d_in[5];
    const float* w_ih1  = (const float*)d_in[6];
    const float* w_hh1  = (const float*)d_in[7];
    const float* b_ih1  = (const float*)d_in[8];
    const float* b_hh1  = (const float*)d_in[9];
    const float* fc_w   = (const float*)d_in[10];
    const float* fc_b   = (const float*)d_in[11];
    const float* pw_ih0 = (const float*)d_in[12];
    const float* pw_hh0 = (const float*)d_in[13];
    const float* pb_ih0 = (const float*)d_in[14];
    const float* pb_hh0 = (const float*)d_in[15];
    const float* pw_ih1 = (const float*)d_in[16];
    const float* pw_hh1 = (const float*)d_in[17];
    const float* pb_ih1 = (const float*)d_in[18];
    const float* pb_hh1 = (const float*)d_in[19];
    const float* pfc_w  = (const float*)d_in[20];
    const float* pfc_b  = (const float*)d_in[21];

    init_kernel<<<256, 256>>>();
    lstm_kernel<<<NCTA, NTHR, SMEM_BYTES>>>(
        x, w_ih0, w_hh0, b_ih0, b_hh0, w_ih1, w_hh1, b_ih1, b_hh1,
        fc_w, fc_b, pw_ih0, pw_hh0, pb_ih0, pb_hh0, pw_ih1, pw_hh1,
        pb_ih1, pb_hh1, pfc_w, pfc_b, (float*)d_out);
}

// round 5
// speedup vs baseline: 2.9456x; 2.9456x over previous
#include <cuda_runtime.h>
#include <cstdint>

#define BATCH 256
#define TSEQ  512
#define HID   512
#define FUT   64
#define NCTA  128
#define NTHR  256
#define MB    64            // batch rows per CTA
#define KC    128           // K chunk
#define KCP   132           // padded chunk pitch (floats); 132 % 32 == 4 -> conflict-free frags
#define ABUF  (64 * KCP)    // one smem buffer (A or B): 64 rows x KCP
#define SHC_PITCH 68
#define SMEM_FLOATS (4 * ABUF + 64 * SHC_PITCH)
#define SMEM_BYTES  (SMEM_FLOATS * 4)   // 152,576 B

// ---------------- persistent device state ----------------
__device__ float g_h0[2][BATCH * HID];
__device__ float g_h1[2][BATCH * HID];
__device__ float g_c0[BATCH * HID];
__device__ float g_c1[BATCH * HID];
__device__ float g_o[BATCH];
__device__ unsigned g_arrive;
__device__ unsigned g_release;
// tf32-pre-rounded GEMM weights: 0=w_hh0 1=w_ih1 2=w_hh1 3=pw_hh0 4=pw_ih1 5=pw_hh1
__device__ float g_wr[6][4 * HID * HID];

// ---------------- helpers ----------------
__device__ __forceinline__ void cp16(float* dst_smem, const float* src_gmem) {
    unsigned d = (unsigned)__cvta_generic_to_shared(dst_smem);
    asm volatile("cp.async.cg.shared.global [%0], [%1], 16;" :: "r"(d), "l"(src_gmem));
}
__device__ __forceinline__ void cp_commit() { asm volatile("cp.async.commit_group;"); }

__device__ __forceinline__ float sgm(float x) { return 1.0f / (1.0f + expf(-x)); }

__device__ __forceinline__ float rn_tf32(float x) {
    uint32_t u; asm("cvt.rna.tf32.f32 %0, %1;" : "=r"(u) : "f"(x));
    return __uint_as_float(u);
}

// grid-wide barrier (monotonic counters; reset by init kernel each launch)
__device__ __forceinline__ void gbar(unsigned& gen) {
    gen++;
    __syncthreads();
    if (threadIdx.x == 0) {
        __threadfence();
        unsigned a = atomicAdd(&g_arrive, 1u) + 1u;
        if (a == (unsigned)NCTA * gen) {
            atomicExch(&g_release, gen);
        } else {
            while (*((volatile unsigned*)&g_release) < gen) { __nanosleep(32); }
        }
        __threadfence();
    }
    __syncthreads();
}

// tf32 mma: D(16x8) += A(16x8) * B(8x8)
__device__ __forceinline__ void mma8(float* c, const uint32_t* a, const uint32_t* b) {
    asm volatile(
        "mma.sync.aligned.m16n8k8.row.col.f32.tf32.tf32.f32 "
        "{%0,%1,%2,%3}, {%4,%5,%6,%7}, {%8,%9}, {%0,%1,%2,%3};\n"
        : "+f"(c[0]), "+f"(c[1]), "+f"(c[2]), "+f"(c[3])
        : "r"(a[0]), "r"(a[1]), "r"(a[2]), "r"(a[3]), "r"(b[0]), "r"(b[1]));
}

// stage one K-chunk: A = h tile rows [0..63] of Asrc, B = 64 gate rows of Wsrc slice
__device__ __forceinline__ void stage_chunk(float* dstA, float* dstB,
                                            const float* Asrc, const float* Wsrc,
                                            int u0, int kc0, int tid) {
#pragma unroll
    for (int i = 0; i < 8; i++) {
        int f4 = tid + i * NTHR;      // 2048 float4 = 64 rows x 32
        int r = f4 >> 5, c4 = f4 & 31;
        cp16(dstA + r * KCP + c4 * 4, Asrc + (size_t)r * HID + kc0 + c4 * 4);
    }
#pragma unroll
    for (int i = 0; i < 8; i++) {
        int f4 = tid + i * NTHR;
        int r = f4 >> 5, c4 = f4 & 31;
        int q = r >> 4, jj = r & 15;  // smem row r = q*16+jj  <-> W row q*HID+u0+jj
        cp16(dstB + r * KCP + c4 * 4, Wsrc + (size_t)(q * HID + u0 + jj) * HID + kc0 + c4 * 4);
    }
    cp_commit();
}

// one K=512 GEMM: cfr += h[64xK] @ Wslice[64xK]^T   (tf32 tensor cores)
__device__ __forceinline__ void gemm_tf32(float (&cfr)[2][2][4],
                                          const float* Asrc, const float* Wsrc, int u0,
                                          float* shA, float* shB,
                                          int tid, int wm, int wn, int gid, int tid4) {
    stage_chunk(shA, shB, Asrc, Wsrc, u0, 0, tid);
    stage_chunk(shA + ABUF, shB + ABUF, Asrc, Wsrc, u0, KC, tid);
#pragma unroll 1
    for (int ch = 0; ch < 4; ch++) {
        if (ch < 3) asm volatile("cp.async.wait_group 1;");
        else        asm volatile("cp.async.wait_group 0;");
        __syncthreads();
        const float* A  = shA + (ch & 1) * ABUF;
        const float* B  = shB + (ch & 1) * ABUF;
        const float* Ab = A + (wm * 32 + gid) * KCP + tid4;
        const float* Bb = B + (wn * 16 + gid) * KCP + tid4;
#pragma unroll
        for (int k8 = 0; k8 < KC / 8; k8++) {
            int kk = k8 * 8;
            uint32_t a[2][4], b[2][2];
#pragma unroll
            for (int ms = 0; ms < 2; ms++) {
                const float* p = Ab + ms * 16 * KCP + kk;
                a[ms][0] = __float_as_uint(p[0]);
                a[ms][1] = __float_as_uint(p[8 * KCP]);
                a[ms][2] = __float_as_uint(p[4]);
                a[ms][3] = __float_as_uint(p[8 * KCP + 4]);
            }
#pragma unroll
            for (int ns = 0; ns < 2; ns++) {
                const float* p = Bb + ns * 8 * KCP + kk;
                b[ns][0] = __float_as_uint(p[0]);
                b[ns][1] = __float_as_uint(p[4]);
            }
#pragma unroll
            for (int ms = 0; ms < 2; ms++)
#pragma unroll
                for (int ns = 0; ns < 2; ns++)
                    mma8(cfr[ms][ns], a[ms], b[ns]);
        }
        __syncthreads();
        if (ch + 2 < 4)
            stage_chunk(shA + (ch & 1) * ABUF, shB + (ch & 1) * ABUF, Asrc, Wsrc, u0,
                        (ch + 2) * KC, tid);
    }
}

__device__ __forceinline__ void zero_c(float (&cfr)[2][2][4]) {
#pragma unroll
    for (int ms = 0; ms < 2; ms++)
#pragma unroll
        for (int ns = 0; ns < 2; ns++)
#pragma unroll
            for (int r = 0; r < 4; r++) cfr[ms][ns][r] = 0.0f;
}

// scatter C fragments to shC[batch][gaterow] for the pointwise update
__device__ __forceinline__ void dump_c(const float (&cfr)[2][2][4], float* shC,
                                       int wm, int wn, int gid, int tid4) {
#pragma unroll
    for (int ms = 0; ms < 2; ms++)
#pragma unroll
        for (int ns = 0; ns < 2; ns++) {
            int row = wm * 32 + ms * 16 + gid;
            int col = wn * 16 + ns * 8 + 2 * tid4;
            *(float2*)(shC + row * SHC_PITCH + col)       = make_float2(cfr[ms][ns][0], cfr[ms][ns][1]);
            *(float2*)(shC + (row + 8) * SHC_PITCH + col) = make_float2(cfr[ms][ns][2], cfr[ms][ns][3]);
        }
}

// pointwise LSTM update; thread owns unit jj (4 batch rows). h stored tf32-rounded.
__device__ __forceinline__ void cell_update(const float* shC, const float bs[4],
                                            const float* xinv, const float xw[4],
                                            float* cbuf, float* hout,
                                            int b0, int bq, int jj, int ju) {
#pragma unroll
    for (int i = 0; i < 4; i++) {
        int bb = bq * 4 + i;
        float pi = shC[bb * SHC_PITCH +  0 + jj] + bs[0];
        float pf = shC[bb * SHC_PITCH + 16 + jj] + bs[1];
        float pg = shC[bb * SHC_PITCH + 32 + jj] + bs[2];
        float po = shC[bb * SHC_PITCH + 48 + jj] + bs[3];
        if (xinv) {
            float xv = xinv[i];
            pi += xv * xw[0]; pf += xv * xw[1]; pg += xv * xw[2]; po += xv * xw[3];
        }
        size_t idx = (size_t)(b0 + bb) * HID + ju;
        float cc = sgm(pf) * cbuf[idx] + sgm(pi) * tanhf(pg);
        cbuf[idx] = cc;
        __stcg(hout + idx, rn_tf32(sgm(po) * tanhf(cc)));
    }
}

// out[:, s] = hbuf @ wvec + bias ; also stashes to g_o
__device__ __forceinline__ void head_dot(const float* hbuf, const float* wvec, const float* bias,
                                         float* out, int s, int b0, int tid) {
    int warp = tid >> 5, lane = tid & 31;
    float bv = __ldg(bias);
    for (int bb = warp; bb < MB; bb += 8) {
        int b = b0 + bb;
        const float4* hp  = (const float4*)(hbuf + (size_t)b * HID);
        const float4* wp4 = (const float4*)wvec;
        float s4 = 0.0f;
#pragma unroll
        for (int rr = 0; rr < 4; rr++) {
            float4 hv = __ldcg(hp + rr * 32 + lane);
            float4 wv = __ldg(wp4 + rr * 32 + lane);
            s4 += hv.x * wv.x + hv.y * wv.y + hv.z * wv.z + hv.w * wv.w;
        }
#pragma unroll
        for (int off = 16; off; off >>= 1) s4 += __shfl_xor_sync(0xffffffffu, s4, off);
        if (lane == 0) {
            float o = s4 + bv;
            out[b * FUT + s] = o;
            g_o[b] = o;
        }
    }
}

// ---------------- kernels ----------------
__global__ void init_kernel(const float* w0, const float* w1, const float* w2,
                            const float* w3, const float* w4, const float* w5) {
    const float* src[6] = {w0, w1, w2, w3, w4, w5};
    size_t i0 = blockIdx.x * (size_t)blockDim.x + threadIdx.x;
    size_t stride = (size_t)gridDim.x * blockDim.x;
    const size_t WN = (size_t)4 * HID * HID;
#pragma unroll 1
    for (int m = 0; m < 6; m++) {
        const float* s = src[m];
        float* d = g_wr[m];
        for (size_t i = i0; i < WN; i += stride) d[i] = rn_tf32(s[i]);
    }
    size_t n = (size_t)BATCH * HID;
    for (size_t k = i0; k < n; k += stride) {
        g_h0[0][k] = 0.f; g_h0[1][k] = 0.f;
        g_h1[0][k] = 0.f; g_h1[1][k] = 0.f;
        g_c0[k] = 0.f;    g_c1[k] = 0.f;
    }
    if (i0 == 0) { g_arrive = 0u; g_release = 0u; }
}

__global__ void __launch_bounds__(NTHR, 1)
lstm_kernel(const float* __restrict__ x,
            const float* __restrict__ w_ih0,
            const float* __restrict__ b_ih0, const float* __restrict__ b_hh0,
            const float* __restrict__ b_ih1, const float* __restrict__ b_hh1,
            const float* __restrict__ fc_w,  const float* __restrict__ fc_b,
            const float* __restrict__ pw_ih0,
            const float* __restrict__ pb_ih0, const float* __restrict__ pb_hh0,
            const float* __restrict__ pb_ih1, const float* __restrict__ pb_hh1,
            const float* __restrict__ pfc_w,  const float* __restrict__ pfc_b,
            float* __restrict__ out) {
    extern __shared__ float smem[];
    float* shA = smem;                 // 2 x ABUF
    float* shB = smem + 2 * ABUF;      // 2 x ABUF
    float* shC = smem + 4 * ABUF;      // 64 x SHC_PITCH

    const int tid  = threadIdx.x;
    const int bt   = blockIdx.x & 3;        // batch tile
    const int sl   = blockIdx.x >> 2;       // hidden slice (16 units)
    const int b0   = bt * MB;
    const int u0   = sl * 16;
    const int wid  = tid >> 5;
    const int wm   = wid & 1;               // batch half (32 rows)
    const int wn   = wid >> 1;              // gate quarter (16 cols)
    const int gid  = (tid & 31) >> 2;
    const int tid4 = tid & 3;
    // update-phase ownership (decoupled from mma frags via shC)
    const int jj = tid & 15;
    const int bq = tid >> 4;
    const int ju = u0 + jj;

    float bs0[4], bs1[4], pbs0[4], pbs1[4], wi0[4], pwi0[4];
#pragma unroll
    for (int q = 0; q < 4; q++) {
        int r = q * HID + ju;
        bs0[q]  = __ldg(b_ih0 + r)  + __ldg(b_hh0 + r);
        bs1[q]  = __ldg(b_ih1 + r)  + __ldg(b_hh1 + r);
        pbs0[q] = __ldg(pb_ih0 + r) + __ldg(pb_hh0 + r);
        pbs1[q] = __ldg(pb_ih1 + r) + __ldg(pb_hh1 + r);
        wi0[q]  = __ldg(w_ih0 + r);
        pwi0[q] = __ldg(pw_ih0 + r);
    }

    unsigned gen = 0;
    int p = 0;
    float cfr[2][2][4];

    // ---------------- warmup over observed sequence ----------------
    for (int t = 0; t < TSEQ; t++) {
        gbar(gen);
        // layer 0
        zero_c(cfr);
        gemm_tf32(cfr, g_h0[p] + (size_t)b0 * HID, g_wr[0], u0, shA, shB, tid, wm, wn, gid, tid4);
        dump_c(cfr, shC, wm, wn, gid, tid4);
        __syncthreads();
        {
            float xin[4];
#pragma unroll
            for (int i = 0; i < 4; i++)
                xin[i] = __ldg(x + (size_t)(b0 + bq * 4 + i) * TSEQ + t);
            cell_update(shC, bs0, xin, wi0, g_c0, g_h0[p ^ 1], b0, bq, jj, ju);
        }
        gbar(gen);
        // layer 1 (two GEMMs accumulate)
        zero_c(cfr);
        gemm_tf32(cfr, g_h0[p ^ 1] + (size_t)b0 * HID, g_wr[1], u0, shA, shB, tid, wm, wn, gid, tid4);
        gemm_tf32(cfr, g_h1[p]     + (size_t)b0 * HID, g_wr[2], u0, shA, shB, tid, wm, wn, gid, tid4);
        dump_c(cfr, shC, wm, wn, gid, tid4);
        __syncthreads();
        cell_update(shC, bs1, (const float*)0, bs1 /*unused*/, g_c1, g_h1[p ^ 1], b0, bq, jj, ju);
        p ^= 1;
    }

    gbar(gen);
    if (sl == 0) head_dot(g_h1[p], fc_w, fc_b, out, 0, b0, tid);

    // ---------------- autoregressive prediction ----------------
    for (int s = 1; s < FUT; s++) {
        gbar(gen);
        // pred layer 0
        zero_c(cfr);
        gemm_tf32(cfr, g_h0[p] + (size_t)b0 * HID, g_wr[3], u0, shA, shB, tid, wm, wn, gid, tid4);
        dump_c(cfr, shC, wm, wn, gid, tid4);
        __syncthreads();
        {
            float xin[4];
#pragma unroll
            for (int i = 0; i < 4; i++)
                xin[i] = __ldcg(&g_o[b0 + bq * 4 + i]);
            cell_update(shC, pbs0, xin, pwi0, g_c0, g_h0[p ^ 1], b0, bq, jj, ju);
        }
        gbar(gen);
        // pred layer 1
        zero_c(cfr);
        gemm_tf32(cfr, g_h0[p ^ 1] + (size_t)b0 * HID, g_wr[4], u0, shA, shB, tid, wm, wn, gid, tid4);
        gemm_tf32(cfr, g_h1[p]     + (size_t)b0 * HID, g_wr[5], u0, shA, shB, tid, wm, wn, gid, tid4);
        dump_c(cfr, shC, wm, wn, gid, tid4);
        __syncthreads();
        cell_update(shC, pbs1, (const float*)0, pbs1 /*unused*/, g_c1, g_h1[p ^ 1], b0, bq, jj, ju);
        gbar(gen);
        if (sl == 0) head_dot(g_h1[p ^ 1], pfc_w, pfc_b, out, s, b0, tid);
        p ^= 1;
    }
}

// ---------------- launch ----------------
extern "C" void kernel_launch(void* const* d_in, const int* in_sizes, int n_in,
                              void* d_out, int out_size) {
    (void)in_sizes; (void)n_in; (void)out_size;
    cudaFuncSetAttribute(lstm_kernel, cudaFuncAttributeMaxDynamicSharedMemorySize, SMEM_BYTES);

    const float* x      = (const float*)d_in[0];
    // d_in[1] = future (scalar) — fixed shapes, FUT hardcoded
    const float* w_ih0  = (const float*)d_in[2];
    const float* w_hh0  = (const float*)d_in[3];
    const float* b_ih0  = (const float*)d_in[4];
    const float* b_hh0  = (const float*)d_in[5];
    const float* w_ih1  = (const float*)d_in[6];
    const float* w_hh1  = (const float*)d_in[7];
    const float* b_ih1  = (const float*)d_in[8];
    const float* b_hh1  = (const float*)d_in[9];
    const float* fc_w   = (const float*)d_in[10];
    const float* fc_b   = (const float*)d_in[11];
    const float* pw_ih0 = (const float*)d_in[12];
    const float* pw_hh0 = (const float*)d_in[13];
    const float* pb_ih0 = (const float*)d_in[14];
    const float* pb_hh0 = (const float*)d_in[15];
    const float* pw_ih1 = (const float*)d_in[16];
    const float* pw_hh1 = (const float*)d_in[17];
    const float* pb_ih1 = (const float*)d_in[18];
    const float* pb_hh1 = (const float*)d_in[19];
    const float* pfc_w  = (const float*)d_in[20];
    const float* pfc_b  = (const float*)d_in[21];

    // pre-round GEMM weights to tf32 + zero state + reset barrier counters
    init_kernel<<<1024, 256>>>(w_hh0, w_ih1, w_hh1, pw_hh0, pw_ih1, pw_hh1);

    lstm_kernel<<<NCTA, NTHR, SMEM_BYTES>>>(
        x, w_ih0, b_ih0, b_hh0, b_ih1, b_hh1, fc_w, fc_b,
        pw_ih0, pb_ih0, pb_hh0, pb_ih1, pb_hh1, pfc_w, pfc_b, (float*)d_out);
}

// round 12
// speedup vs baseline: 4.0999x; 1.3919x over previous
#include <cuda_runtime.h>
#include <cuda_fp16.h>
#include <cstdint>

#define BATCH 256
#define TSEQ  512
#define HID   512
#define FUT   64
#define NCTA  128
#define NTHR  256
#define MB    64                   // batch rows per CTA (R5 layout)
#define UH    16                   // hidden units per CTA slice (R5 layout)
#define KC    128                  // K chunk (halfs)
#define CP    136                  // chunk row pitch (halfs); 68 words/row = 4 banks -> conflict-free
#define CBUF  (64 * CP)            // one staging buffer (A or B): 64 rows x CP = 8704 halfs
#define SHC_PITCH 68
#define SMEM_BYTES ((4 * CBUF) * 2 + 64 * SHC_PITCH * 4)   // 87,040 B

// ---------------- persistent device state ----------------
__device__ __half g_h0[2][BATCH * HID];
__device__ __half g_h1[2][BATCH * HID];
__device__ float  g_c0[BATCH * HID];
__device__ float  g_c1[BATCH * HID];
__device__ float  g_o[BATCH];
__device__ unsigned g_arrive;
__device__ unsigned g_release;
// fp16 weights: 0=w_hh0 1=w_ih1 2=w_hh1 3=pw_hh0 4=pw_ih1 5=pw_hh1
__device__ __half g_wh[6][4 * HID * HID];

// ---------------- helpers ----------------
__device__ __forceinline__ void cp16(void* dst_smem, const void* src_gmem) {
    unsigned d = (unsigned)__cvta_generic_to_shared(dst_smem);
    asm volatile("cp.async.cg.shared.global [%0], [%1], 16;" :: "r"(d), "l"(src_gmem));
}
__device__ __forceinline__ void cp_commit() { asm volatile("cp.async.commit_group;"); }

__device__ __forceinline__ float sgm(float x) { return 1.0f / (1.0f + expf(-x)); }

__device__ __forceinline__ void sthcg(__half* p, float v) {
    __half h = __float2half_rn(v);
    unsigned short u = *(unsigned short*)&h;
    asm volatile("st.global.cg.u16 [%0], %1;" :: "l"(p), "h"(u));
}
__device__ __forceinline__ float ldhcg(const __half* p) {
    unsigned short u;
    asm volatile("ld.global.cg.u16 %0, [%1];" : "=h"(u) : "l"(p));
    __half h = *(__half*)&u;
    return __half2float(h);
}

// grid-wide barrier (monotonic; reset by init kernel each launch) — R5 verbatim
__device__ __forceinline__ void gbar(unsigned& gen) {
    gen++;
    __syncthreads();
    if (threadIdx.x == 0) {
        __threadfence();
        unsigned a = atomicAdd(&g_arrive, 1u) + 1u;
        if (a == (unsigned)NCTA * gen) {
            atomicExch(&g_release, gen);
        } else {
            while (*((volatile unsigned*)&g_release) < gen) { __nanosleep(32); }
        }
        __threadfence();
    }
    __syncthreads();
}

__device__ __forceinline__ void mma16(float* c, uint32_t a0, uint32_t a1, uint32_t a2, uint32_t a3,
                                      uint32_t b0, uint32_t b1) {
    asm volatile(
        "mma.sync.aligned.m16n8k16.row.col.f32.f16.f16.f32 "
        "{%0,%1,%2,%3},{%4,%5,%6,%7},{%8,%9},{%0,%1,%2,%3};"
        : "+f"(c[0]), "+f"(c[1]), "+f"(c[2]), "+f"(c[3])
        : "r"(a0), "r"(a1), "r"(a2), "r"(a3), "r"(b0), "r"(b1));
}

__device__ __forceinline__ uint32_t ld32(const __half* p) {
    return *(const uint32_t*)p;
}

// stage one K-chunk: A = 64 h rows, B = 64 gate rows (4 gates x 16 units) — R5 stage_chunk, fp16
__device__ __forceinline__ void stage_ab(__half* dstA, __half* dstB,
                                         const __half* hsrc, const __half* Wsrc,
                                         int u0, int kc0, int tid) {
#pragma unroll
    for (int i = 0; i < 4; i++) {
        int idx = tid + i * NTHR;       // 1024 x 16B
        int r = idx >> 4, c8 = idx & 15;
        cp16(dstA + r * CP + c8 * 8, hsrc + (size_t)r * HID + kc0 + c8 * 8);
    }
#pragma unroll
    for (int i = 0; i < 4; i++) {
        int idx = tid + i * NTHR;
        int r = idx >> 4, c8 = idx & 15;
        int q = r >> 4, j = r & 15;     // smem row r = q*16+j  <-> W row q*HID+u0+j
        cp16(dstB + r * CP + c8 * 8, Wsrc + (size_t)(q * HID + u0 + j) * HID + kc0 + c8 * 8);
    }
    cp_commit();
}

// one K=512 GEMM: cfr += h[64xK] @ Wslice[64xK]^T  (fp16 HMMA; R5 pipeline structure)
__device__ __forceinline__ void gemm16(float (&cfr)[2][2][4], const __half* hsrc,
                                       const __half* Wsrc, int u0,
                                       __half* shA, __half* shB,
                                       int tid, int aOffH, int bOffH) {
    stage_ab(shA, shB, hsrc, Wsrc, u0, 0, tid);
    stage_ab(shA + CBUF, shB + CBUF, hsrc, Wsrc, u0, KC, tid);
#pragma unroll 1
    for (int ch = 0; ch < 4; ch++) {
        if (ch < 3) asm volatile("cp.async.wait_group 1;");
        else        asm volatile("cp.async.wait_group 0;");
        __syncthreads();
        const __half* Ab = shA + (ch & 1) * CBUF + aOffH;
        const __half* Bb = shB + (ch & 1) * CBUF + bOffH;
#pragma unroll
        for (int k16 = 0; k16 < KC / 16; k16++) {
            const __half* ap = Ab + k16 * 16;
            const __half* bp = Bb + k16 * 16;
            uint32_t a0 = ld32(ap);                 // A[g][2t]
            uint32_t a1 = ld32(ap + 8 * CP);        // A[g+8][2t]
            uint32_t a2 = ld32(ap + 8);             // A[g][2t+8]
            uint32_t a3 = ld32(ap + 8 * CP + 8);    // A[g+8][2t+8]
            uint32_t a4 = ld32(ap + 16 * CP);       // ms=1 tile (+16 rows)
            uint32_t a5 = ld32(ap + 24 * CP);
            uint32_t a6 = ld32(ap + 16 * CP + 8);
            uint32_t a7 = ld32(ap + 24 * CP + 8);
            uint32_t b0 = ld32(bp);                 // W[g][2t]
            uint32_t b1 = ld32(bp + 8);             // W[g][2t+8]
            uint32_t b2 = ld32(bp + 8 * CP);        // ns=1 tile (+8 W rows)
            uint32_t b3 = ld32(bp + 8 * CP + 8);
            mma16(cfr[0][0], a0, a1, a2, a3, b0, b1);
            mma16(cfr[0][1], a0, a1, a2, a3, b2, b3);
            mma16(cfr[1][0], a4, a5, a6, a7, b0, b1);
            mma16(cfr[1][1], a4, a5, a6, a7, b2, b3);
        }
        __syncthreads();
        if (ch + 2 < 4)
            stage_ab(shA + (ch & 1) * CBUF, shB + (ch & 1) * CBUF, hsrc, Wsrc, u0,
                     (ch + 2) * KC, tid);
    }
}

__device__ __forceinline__ void zero_c(float (&cfr)[2][2][4]) {
#pragma unroll
    for (int ms = 0; ms < 2; ms++)
#pragma unroll
        for (int ns = 0; ns < 2; ns++)
#pragma unroll
            for (int r = 0; r < 4; r++) cfr[ms][ns][r] = 0.0f;
}

// scatter C frags to shC[batch][gate_row] — R5 dump_c verbatim (pitch 68, 64 cols)
__device__ __forceinline__ void dump_c(const float (&cfr)[2][2][4], float* shC,
                                       int wm, int wn, int gid, int tid4) {
#pragma unroll
    for (int ms = 0; ms < 2; ms++)
#pragma unroll
        for (int ns = 0; ns < 2; ns++) {
            int row = wm * 32 + ms * 16 + gid;
            int col = wn * 16 + ns * 8 + 2 * tid4;
            *(float2*)(shC + row * SHC_PITCH + col)       = make_float2(cfr[ms][ns][0], cfr[ms][ns][1]);
            *(float2*)(shC + (row + 8) * SHC_PITCH + col) = make_float2(cfr[ms][ns][2], cfr[ms][ns][3]);
        }
}

// pointwise LSTM update — R5 verbatim indexing (gates at cols 0,16,32,48); h stored fp16
__device__ __forceinline__ void cell_update(const float* shC, const float bs[4],
                                            const float* xinv, const float xw[4],
                                            float* cbuf, __half* hout,
                                            int b0, int bq, int jj, int ju) {
#pragma unroll
    for (int i = 0; i < 4; i++) {
        int bb = bq * 4 + i;
        float pi = shC[bb * SHC_PITCH +  0 + jj] + bs[0];
        float pf = shC[bb * SHC_PITCH + 16 + jj] + bs[1];
        float pg = shC[bb * SHC_PITCH + 32 + jj] + bs[2];
        float po = shC[bb * SHC_PITCH + 48 + jj] + bs[3];
        if (xinv) {
            float xv = xinv[i];
            pi += xv * xw[0]; pf += xv * xw[1]; pg += xv * xw[2]; po += xv * xw[3];
        }
        size_t idx = (size_t)(b0 + bb) * HID + ju;
        float cc = sgm(pf) * cbuf[idx] + sgm(pi) * tanhf(pg);
        cbuf[idx] = cc;
        sthcg(hout + idx, sgm(po) * tanhf(cc));
    }
}

// out[:, s] = hbuf @ wvec + bias ; stashes g_o. Deliberately simple scalar fp16 reads.
__device__ __forceinline__ void head_dot(const __half* hbuf, const float* wvec, const float* bias,
                                         float* out, int s, int b0, int tid) {
    int warp = tid >> 5, lane = tid & 31;
    float bv = __ldg(bias);
    for (int bb = warp; bb < MB; bb += 8) {
        int b = b0 + bb;
        float acc = 0.0f;
        for (int k = lane; k < HID; k += 32)
            acc += ldhcg(hbuf + (size_t)b * HID + k) * __ldg(wvec + k);
#pragma unroll
        for (int off = 16; off; off >>= 1) acc += __shfl_xor_sync(0xffffffffu, acc, off);
        if (lane == 0) {
            float o = acc + bv;
            out[b * FUT + s] = o;
            g_o[b] = o;
        }
    }
}

// ---------------- kernels ----------------
__global__ void init_kernel(const float* w0, const float* w1, const float* w2,
                            const float* w3, const float* w4, const float* w5) {
    const float* src[6] = {w0, w1, w2, w3, w4, w5};
    size_t i0 = blockIdx.x * (size_t)blockDim.x + threadIdx.x;
    size_t stride = (size_t)gridDim.x * blockDim.x;
    const size_t WN = (size_t)4 * HID * HID;
#pragma unroll 1
    for (int m = 0; m < 6; m++) {
        const float* s = src[m];
        __half* d = g_wh[m];
        for (size_t i = i0; i < WN; i += stride) d[i] = __float2half_rn(s[i]);
    }
    size_t n = (size_t)BATCH * HID;
    __half hz = __float2half_rn(0.0f);
    for (size_t k = i0; k < n; k += stride) {
        g_h0[0][k] = hz; g_h0[1][k] = hz;
        g_h1[0][k] = hz; g_h1[1][k] = hz;
        g_c0[k] = 0.f;   g_c1[k] = 0.f;
    }
    if (i0 == 0) { g_arrive = 0u; g_release = 0u; }
}

__global__ void __launch_bounds__(NTHR, 1)
lstm_kernel(const float* __restrict__ x,
            const float* __restrict__ w_ih0,
            const float* __restrict__ b_ih0, const float* __restrict__ b_hh0,
            const float* __restrict__ b_ih1, const float* __restrict__ b_hh1,
            const float* __restrict__ fc_w,  const float* __restrict__ fc_b,
            const float* __restrict__ pw_ih0,
            const float* __restrict__ pb_ih0, const float* __restrict__ pb_hh0,
            const float* __restrict__ pb_ih1, const float* __restrict__ pb_hh1,
            const float* __restrict__ pfc_w,  const float* __restrict__ pfc_b,
            float* __restrict__ out) {
    extern __shared__ __half smemh[];
    __half* shA = smemh;                       // 2 x CBUF
    __half* shB = smemh + 2 * CBUF;            // 2 x CBUF
    float*  shC = (float*)(smemh + 4 * CBUF);  // 64 x SHC_PITCH floats

    // ---- R5 thread/grid roles, verbatim ----
    const int tid  = threadIdx.x;
    const int bt   = blockIdx.x & 3;           // 4 batch tiles of 64
    const int sl   = blockIdx.x >> 2;          // 32 hidden slices of 16
    const int b0   = bt * MB;
    const int u0   = sl * UH;
    const int wid  = tid >> 5;
    const int wm   = wid & 1;                  // batch half (32 rows)
    const int wn   = wid >> 1;                 // gate quarter (16 cols)
    const int gid  = (tid & 31) >> 2;
    const int tid4 = tid & 3;
    const int jj   = tid & 15;
    const int bq   = tid >> 4;
    const int ju   = u0 + jj;

    // fp16 fragment base offsets (halfs): A row wm*32+g, B row wn*16+g, col 2t
    const int aOffH = (wm * 32 + gid) * CP + 2 * tid4;
    const int bOffH = (wn * 16 + gid) * CP + 2 * tid4;

    float bs0[4], bs1[4], pbs0[4], pbs1[4], wi0[4], pwi0[4];
#pragma unroll
    for (int q = 0; q < 4; q++) {
        int r = q * HID + ju;
        bs0[q]  = __ldg(b_ih0 + r)  + __ldg(b_hh0 + r);
        bs1[q]  = __ldg(b_ih1 + r)  + __ldg(b_hh1 + r);
        pbs0[q] = __ldg(pb_ih0 + r) + __ldg(pb_hh0 + r);
        pbs1[q] = __ldg(pb_ih1 + r) + __ldg(pb_hh1 + r);
        wi0[q]  = __ldg(w_ih0 + r);
        pwi0[q] = __ldg(pw_ih0 + r);
    }

    unsigned gen = 0;
    int p = 0;
    float cfr[2][2][4];

    // ---------------- warmup over observed sequence ----------------
    for (int t = 0; t < TSEQ; t++) {
        gbar(gen);
        // layer 0
        zero_c(cfr);
        gemm16(cfr, g_h0[p] + (size_t)b0 * HID, g_wh[0], u0, shA, shB, tid, aOffH, bOffH);
        dump_c(cfr, shC, wm, wn, gid, tid4);
        __syncthreads();
        {
            float xin[4];
#pragma unroll
            for (int i = 0; i < 4; i++)
                xin[i] = __ldg(x + (size_t)(b0 + bq * 4 + i) * TSEQ + t);
            cell_update(shC, bs0, xin, wi0, g_c0, g_h0[p ^ 1], b0, bq, jj, ju);
        }
        gbar(gen);
        // layer 1 (two GEMMs accumulate)
        zero_c(cfr);
        gemm16(cfr, g_h0[p ^ 1] + (size_t)b0 * HID, g_wh[1], u0, shA, shB, tid, aOffH, bOffH);
        gemm16(cfr, g_h1[p]     + (size_t)b0 * HID, g_wh[2], u0, shA, shB, tid, aOffH, bOffH);
        dump_c(cfr, shC, wm, wn, gid, tid4);
        __syncthreads();
        cell_update(shC, bs1, (const float*)0, bs1 /*unused*/, g_c1, g_h1[p ^ 1], b0, bq, jj, ju);
        p ^= 1;
    }

    gbar(gen);
    if (sl == 0) head_dot(g_h1[p], fc_w, fc_b, out, 0, b0, tid);

    // ---------------- autoregressive prediction ----------------
    for (int s = 1; s < FUT; s++) {
        gbar(gen);
        // pred layer 0
        zero_c(cfr);
        gemm16(cfr, g_h0[p] + (size_t)b0 * HID, g_wh[3], u0, shA, shB, tid, aOffH, bOffH);
        dump_c(cfr, shC, wm, wn, gid, tid4);
        __syncthreads();
        {
            float xin[4];
#pragma unroll
            for (int i = 0; i < 4; i++)
                xin[i] = __ldcg(&g_o[b0 + bq * 4 + i]);
            cell_update(shC, pbs0, xin, pwi0, g_c0, g_h0[p ^ 1], b0, bq, jj, ju);
        }
        gbar(gen);
        // pred layer 1
        zero_c(cfr);
        gemm16(cfr, g_h0[p ^ 1] + (size_t)b0 * HID, g_wh[4], u0, shA, shB, tid, aOffH, bOffH);
        gemm16(cfr, g_h1[p]     + (size_t)b0 * HID, g_wh[5], u0, shA, shB, tid, aOffH, bOffH);
        dump_c(cfr, shC, wm, wn, gid, tid4);
        __syncthreads();
        cell_update(shC, pbs1, (const float*)0, pbs1 /*unused*/, g_c1, g_h1[p ^ 1], b0, bq, jj, ju);
        gbar(gen);
        if (sl == 0) head_dot(g_h1[p ^ 1], pfc_w, pfc_b, out, s, b0, tid);
        p ^= 1;
    }
}

// ---------------- launch ----------------
extern "C" void kernel_launch(void* const* d_in, const int* in_sizes, int n_in,
                              void* d_out, int out_size) {
    (void)in_sizes; (void)n_in; (void)out_size;
    cudaFuncSetAttribute(lstm_kernel, cudaFuncAttributeMaxDynamicSharedMemorySize, SMEM_BYTES);

    const float* x      = (const float*)d_in[0];
    // d_in[1] = future (scalar) — fixed shapes, FUT hardcoded
    const float* w_ih0  = (const float*)d_in[2];
    const float* w_hh0  = (const float*)d_in[3];
    const float* b_ih0  = (const float*)d_in[4];
    const float* b_hh0  = (const float*)d_in[5];
    const float* w_ih1  = (const float*)d_in[6];
    const float* w_hh1  = (const float*)d_in[7];
    const float* b_ih1  = (const float*)d_in[8];
    const float* b_hh1  = (const float*)d_in[9];
    const float* fc_w   = (const float*)d_in[10];
    const float* fc_b   = (const float*)d_in[11];
    const float* pw_ih0 = (const float*)d_in[12];
    const float* pw_hh0 = (const float*)d_in[13];
    const float* pb_ih0 = (const float*)d_in[14];
    const float* pb_hh0 = (const float*)d_in[15];
    const float* pw_ih1 = (const float*)d_in[16];
    const float* pw_hh1 = (const float*)d_in[17];
    const float* pb_ih1 = (const float*)d_in[18];
    const float* pb_hh1 = (const float*)d_in[19];
    const float* pfc_w  = (const float*)d_in[20];
    const float* pfc_b  = (const float*)d_in[21];

    // fp16 weight conversion + state zero + barrier reset
    init_kernel<<<1024, 256>>>(w_hh0, w_ih1, w_hh1, pw_hh0, pw_ih1, pw_hh1);

    lstm_kernel<<<NCTA, NTHR, SMEM_BYTES>>>(
        x, w_ih0, b_ih0, b_hh0, b_ih1, b_hh1, fc_w, fc_b,
        pw_ih0, pb_ih0, pb_hh0, pb_ih1, pb_hh1, pfc_w, pfc_b, (float*)d_out);
}

// round 13
// speedup vs baseline: 4.3844x; 1.0694x over previous
#include <cuda_runtime.h>
#include <cuda_fp16.h>
#include <cstdint>

#define BATCH 256
#define TSEQ  512
#define HID   512
#define FUT   64
#define NCTA  128
#define NTHR  256
#define MB    64                   // batch rows per CTA (R5 layout)
#define UH    16                   // hidden units per CTA slice (R5 layout)
#define KC    128                  // K chunk (halfs)
#define CP    136                  // chunk row pitch (halfs); 68 words/row = 4 banks -> conflict-free
#define CBUF  (64 * CP)            // one staging buffer (A or B): 64 rows x CP = 8704 halfs
#define SHC_PITCH 68
#define SMEM_BYTES ((4 * CBUF) * 2 + 64 * SHC_PITCH * 4)   // 87,040 B

// ---------------- persistent device state ----------------
__device__ __half g_h0[2][BATCH * HID];
__device__ __half g_h1[2][BATCH * HID];
__device__ float  g_c0[BATCH * HID];
__device__ float  g_c1[BATCH * HID];
__device__ float  g_o[BATCH];
__device__ unsigned g_arrive;
__device__ unsigned g_release;
// fp16 weights: 0=w_hh0 1=w_ih1 2=w_hh1 3=pw_hh0 4=pw_ih1 5=pw_hh1
__device__ __half g_wh[6][4 * HID * HID];

// ---------------- helpers ----------------
__device__ __forceinline__ void cp16(void* dst_smem, const void* src_gmem) {
    unsigned d = (unsigned)__cvta_generic_to_shared(dst_smem);
    asm volatile("cp.async.cg.shared.global [%0], [%1], 16;" :: "r"(d), "l"(src_gmem));
}
__device__ __forceinline__ void cp_commit() { asm volatile("cp.async.commit_group;"); }

__device__ __forceinline__ float sgm(float x) { return 1.0f / (1.0f + expf(-x)); }

__device__ __forceinline__ void sthcg(__half* p, float v) {
    __half h = __float2half_rn(v);
    unsigned short u = *(unsigned short*)&h;
    asm volatile("st.global.cg.u16 [%0], %1;" :: "l"(p), "h"(u));
}
__device__ __forceinline__ float ldhcg(const __half* p) {
    unsigned short u;
    asm volatile("ld.global.cg.u16 %0, [%1];" : "=h"(u) : "l"(p));
    __half h = *(__half*)&u;
    return __half2float(h);
}

// grid-wide barrier (monotonic; reset by init kernel each launch) — R5 verbatim
__device__ __forceinline__ void gbar(unsigned& gen) {
    gen++;
    __syncthreads();
    if (threadIdx.x == 0) {
        __threadfence();
        unsigned a = atomicAdd(&g_arrive, 1u) + 1u;
        if (a == (unsigned)NCTA * gen) {
            atomicExch(&g_release, gen);
        } else {
            while (*((volatile unsigned*)&g_release) < gen) { __nanosleep(32); }
        }
        __threadfence();
    }
    __syncthreads();
}

__device__ __forceinline__ void mma16(float* c, uint32_t a0, uint32_t a1, uint32_t a2, uint32_t a3,
                                      uint32_t b0, uint32_t b1) {
    asm volatile(
        "mma.sync.aligned.m16n8k16.row.col.f32.f16.f16.f32 "
        "{%0,%1,%2,%3},{%4,%5,%6,%7},{%8,%9},{%0,%1,%2,%3};"
        : "+f"(c[0]), "+f"(c[1]), "+f"(c[2]), "+f"(c[3])
        : "r"(a0), "r"(a1), "r"(a2), "r"(a3), "r"(b0), "r"(b1));
}

__device__ __forceinline__ void ldsm4(uint32_t& r0, uint32_t& r1, uint32_t& r2, uint32_t& r3,
                                      uint32_t addr) {
    asm volatile("ldmatrix.sync.aligned.m8n8.x4.shared.b16 {%0,%1,%2,%3}, [%4];"
                 : "=r"(r0), "=r"(r1), "=r"(r2), "=r"(r3) : "r"(addr));
}

// stage one K-chunk: A = 64 h rows, B = 64 gate rows (4 gates x 16 units) — R5 stage_chunk, fp16
__device__ __forceinline__ void stage_ab(__half* dstA, __half* dstB,
                                         const __half* hsrc, const __half* Wsrc,
                                         int u0, int kc0, int tid) {
#pragma unroll
    for (int i = 0; i < 4; i++) {
        int idx = tid + i * NTHR;       // 1024 x 16B
        int r = idx >> 4, c8 = idx & 15;
        cp16(dstA + r * CP + c8 * 8, hsrc + (size_t)r * HID + kc0 + c8 * 8);
    }
#pragma unroll
    for (int i = 0; i < 4; i++) {
        int idx = tid + i * NTHR;
        int r = idx >> 4, c8 = idx & 15;
        int q = r >> 4, j = r & 15;     // smem row r = q*16+j  <-> W row q*HID+u0+j
        cp16(dstB + r * CP + c8 * 8, Wsrc + (size_t)(q * HID + u0 + j) * HID + kc0 + c8 * 8);
    }
    cp_commit();
}

// one K=512 GEMM: cfr += h[64xK] @ Wslice[64xK]^T  (fp16 HMMA; ldmatrix-fed fragments)
// A ldsm.x4: lanes 0-7 -> m0 rows[0:8)k[0:8); 8-15 -> m1 rows[8:16)k[0:8);
//            16-23 -> m2 rows[0:8)k[8:16); 24-31 -> m3 rows[8:16)k[8:16)  => regs a0..a3
// B ldsm.x4: m0 = Wrows[0:8)k[0:8)=b0(ns0); m1 = Wrows[0:8)k[8:16)=b1(ns0);
//            m2 = Wrows[8:16)k[0:8)=b0(ns1); m3 = Wrows[8:16)k[8:16)=b1(ns1)
__device__ __forceinline__ void gemm16(float (&cfr)[2][2][4], const __half* hsrc,
                                       const __half* Wsrc, int u0,
                                       __half* shA, __half* shB,
                                       int tid, uint32_t aAddr0, uint32_t bAddr0) {
    stage_ab(shA, shB, hsrc, Wsrc, u0, 0, tid);
    stage_ab(shA + CBUF, shB + CBUF, hsrc, Wsrc, u0, KC, tid);
#pragma unroll 1
    for (int ch = 0; ch < 4; ch++) {
        if (ch < 3) asm volatile("cp.async.wait_group 1;");
        else        asm volatile("cp.async.wait_group 0;");
        __syncthreads();
        const uint32_t Ab = aAddr0 + (uint32_t)(ch & 1) * (CBUF * 2);
        const uint32_t Bb = bAddr0 + (uint32_t)(ch & 1) * (CBUF * 2);
#pragma unroll
        for (int k16 = 0; k16 < KC / 16; k16++) {
            uint32_t kb = (uint32_t)k16 * 32;        // 16 halfs = 32 B
            uint32_t a0, a1, a2, a3, a4, a5, a6, a7, b0, b1, b2, b3;
            ldsm4(a0, a1, a2, a3, Ab + kb);                   // ms=0 tile
            ldsm4(a4, a5, a6, a7, Ab + 16 * CP * 2 + kb);     // ms=1 tile (+16 rows)
            ldsm4(b0, b1, b2, b3, Bb + kb);                   // both n-tiles
            mma16(cfr[0][0], a0, a1, a2, a3, b0, b1);
            mma16(cfr[0][1], a0, a1, a2, a3, b2, b3);
            mma16(cfr[1][0], a4, a5, a6, a7, b0, b1);
            mma16(cfr[1][1], a4, a5, a6, a7, b2, b3);
        }
        __syncthreads();
        if (ch + 2 < 4)
            stage_ab(shA + (ch & 1) * CBUF, shB + (ch & 1) * CBUF, hsrc, Wsrc, u0,
                     (ch + 2) * KC, tid);
    }
}

__device__ __forceinline__ void zero_c(float (&cfr)[2][2][4]) {
#pragma unroll
    for (int ms = 0; ms < 2; ms++)
#pragma unroll
        for (int ns = 0; ns < 2; ns++)
#pragma unroll
            for (int r = 0; r < 4; r++) cfr[ms][ns][r] = 0.0f;
}

// scatter C frags to shC[batch][gate_row] — R5 dump_c verbatim (pitch 68, 64 cols)
__device__ __forceinline__ void dump_c(const float (&cfr)[2][2][4], float* shC,
                                       int wm, int wn, int gid, int tid4) {
#pragma unroll
    for (int ms = 0; ms < 2; ms++)
#pragma unroll
        for (int ns = 0; ns < 2; ns++) {
            int row = wm * 32 + ms * 16 + gid;
            int col = wn * 16 + ns * 8 + 2 * tid4;
            *(float2*)(shC + row * SHC_PITCH + col)       = make_float2(cfr[ms][ns][0], cfr[ms][ns][1]);
            *(float2*)(shC + (row + 8) * SHC_PITCH + col) = make_float2(cfr[ms][ns][2], cfr[ms][ns][3]);
        }
}

// pointwise LSTM update — R5 verbatim indexing (gates at cols 0,16,32,48); h stored fp16
__device__ __forceinline__ void cell_update(const float* shC, const float bs[4],
                                            const float* xinv, const float xw[4],
                                            float* cbuf, __half* hout,
                                            int b0, int bq, int jj, int ju) {
#pragma unroll
    for (int i = 0; i < 4; i++) {
        int bb = bq * 4 + i;
        float pi = shC[bb * SHC_PITCH +  0 + jj] + bs[0];
        float pf = shC[bb * SHC_PITCH + 16 + jj] + bs[1];
        float pg = shC[bb * SHC_PITCH + 32 + jj] + bs[2];
        float po = shC[bb * SHC_PITCH + 48 + jj] + bs[3];
        if (xinv) {
            float xv = xinv[i];
            pi += xv * xw[0]; pf += xv * xw[1]; pg += xv * xw[2]; po += xv * xw[3];
        }
        size_t idx = (size_t)(b0 + bb) * HID + ju;
        float cc = sgm(pf) * cbuf[idx] + sgm(pi) * tanhf(pg);
        cbuf[idx] = cc;
        sthcg(hout + idx, sgm(po) * tanhf(cc));
    }
}

// out[:, s] = hbuf @ wvec + bias ; stashes g_o. Deliberately simple scalar fp16 reads.
__device__ __forceinline__ void head_dot(const __half* hbuf, const float* wvec, const float* bias,
                                         float* out, int s, int b0, int tid) {
    int warp = tid >> 5, lane = tid & 31;
    float bv = __ldg(bias);
    for (int bb = warp; bb < MB; bb += 8) {
        int b = b0 + bb;
        float acc = 0.0f;
        for (int k = lane; k < HID; k += 32)
            acc += ldhcg(hbuf + (size_t)b * HID + k) * __ldg(wvec + k);
#pragma unroll
        for (int off = 16; off; off >>= 1) acc += __shfl_xor_sync(0xffffffffu, acc, off);
        if (lane == 0) {
            float o = acc + bv;
            out[b * FUT + s] = o;
            g_o[b] = o;
        }
    }
}

// ---------------- kernels ----------------
__global__ void init_kernel(const float* w0, const float* w1, const float* w2,
                            const float* w3, const float* w4, const float* w5) {
    const float* src[6] = {w0, w1, w2, w3, w4, w5};
    size_t i0 = blockIdx.x * (size_t)blockDim.x + threadIdx.x;
    size_t stride = (size_t)gridDim.x * blockDim.x;
    const size_t WN = (size_t)4 * HID * HID;
#pragma unroll 1
    for (int m = 0; m < 6; m++) {
        const float* s = src[m];
        __half* d = g_wh[m];
        for (size_t i = i0; i < WN; i += stride) d[i] = __float2half_rn(s[i]);
    }
    size_t n = (size_t)BATCH * HID;
    __half hz = __float2half_rn(0.0f);
    for (size_t k = i0; k < n; k += stride) {
        g_h0[0][k] = hz; g_h0[1][k] = hz;
        g_h1[0][k] = hz; g_h1[1][k] = hz;
        g_c0[k] = 0.f;   g_c1[k] = 0.f;
    }
    if (i0 == 0) { g_arrive = 0u; g_release = 0u; }
}

__global__ void __launch_bounds__(NTHR, 1)
lstm_kernel(const float* __restrict__ x,
            const float* __restrict__ w_ih0,
            const float* __restrict__ b_ih0, const float* __restrict__ b_hh0,
            const float* __restrict__ b_ih1, const float* __restrict__ b_hh1,
            const float* __restrict__ fc_w,  const float* __restrict__ fc_b,
            const float* __restrict__ pw_ih0,
            const float* __restrict__ pb_ih0, const float* __restrict__ pb_hh0,
            const float* __restrict__ pb_ih1, const float* __restrict__ pb_hh1,
            const float* __restrict__ pfc_w,  const float* __restrict__ pfc_b,
            float* __restrict__ out) {
    extern __shared__ __half smemh[];
    __half* shA = smemh;                       // 2 x CBUF
    __half* shB = smemh + 2 * CBUF;            // 2 x CBUF
    float*  shC = (float*)(smemh + 4 * CBUF);  // 64 x SHC_PITCH floats

    // ---- R5 thread/grid roles, verbatim ----
    const int tid  = threadIdx.x;
    const int lane = tid & 31;
    const int bt   = blockIdx.x & 3;           // 4 batch tiles of 64
    const int sl   = blockIdx.x >> 2;          // 32 hidden slices of 16
    const int b0   = bt * MB;
    const int u0   = sl * UH;
    const int wid  = tid >> 5;
    const int wm   = wid & 1;                  // batch half (32 rows)
    const int wn   = wid >> 1;                 // gate quarter (16 cols)
    const int gid  = lane >> 2;
    const int tid4 = lane & 3;
    const int jj   = tid & 15;
    const int bq   = tid >> 4;
    const int ju   = u0 + jj;

    // ldmatrix per-lane base addresses (bytes, shared space)
    const uint32_t shA_u = (uint32_t)__cvta_generic_to_shared(shA);
    const uint32_t shB_u = (uint32_t)__cvta_generic_to_shared(shB);
    const int r8 = lane & 7;
    // A: m0/m1 select rows +0/+8 via (lane>>3)&1; m2/m3 select k +8 halfs via lane>>4
    const uint32_t aAddr0 = shA_u +
        (uint32_t)(((wm * 32 + ((lane >> 3) & 1) * 8 + r8) * CP + (lane >> 4) * 8) * 2);
    // B: m0/m1 = rows[0:8) k 0/+8; m2/m3 = rows[8:16) k 0/+8
    const uint32_t bAddr0 = shB_u +
        (uint32_t)(((wn * 16 + (lane >> 4) * 8 + r8) * CP + ((lane >> 3) & 1) * 8) * 2);

    float bs0[4], bs1[4], pbs0[4], pbs1[4], wi0[4], pwi0[4];
#pragma unroll
    for (int q = 0; q < 4; q++) {
        int r = q * HID + ju;
        bs0[q]  = __ldg(b_ih0 + r)  + __ldg(b_hh0 + r);
        bs1[q]  = __ldg(b_ih1 + r)  + __ldg(b_hh1 + r);
        pbs0[q] = __ldg(pb_ih0 + r) + __ldg(pb_hh0 + r);
        pbs1[q] = __ldg(pb_ih1 + r) + __ldg(pb_hh1 + r);
        wi0[q]  = __ldg(w_ih0 + r);
        pwi0[q] = __ldg(pw_ih0 + r);
    }

    unsigned gen = 0;
    int p = 0;
    float cfr[2][2][4];

    // ---------------- warmup over observed sequence ----------------
    for (int t = 0; t < TSEQ; t++) {
        gbar(gen);
        // layer 0
        zero_c(cfr);
        gemm16(cfr, g_h0[p] + (size_t)b0 * HID, g_wh[0], u0, shA, shB, tid, aAddr0, bAddr0);
        dump_c(cfr, shC, wm, wn, gid, tid4);
        __syncthreads();
        {
            float xin[4];
#pragma unroll
            for (int i = 0; i < 4; i++)
                xin[i] = __ldg(x + (size_t)(b0 + bq * 4 + i) * TSEQ + t);
            cell_update(shC, bs0, xin, wi0, g_c0, g_h0[p ^ 1], b0, bq, jj, ju);
        }
        gbar(gen);
        // layer 1 (two GEMMs accumulate)
        zero_c(cfr);
        gemm16(cfr, g_h0[p ^ 1] + (size_t)b0 * HID, g_wh[1], u0, shA, shB, tid, aAddr0, bAddr0);
        gemm16(cfr, g_h1[p]     + (size_t)b0 * HID, g_wh[2], u0, shA, shB, tid, aAddr0, bAddr0);
        dump_c(cfr, shC, wm, wn, gid, tid4);
        __syncthreads();
        cell_update(shC, bs1, (const float*)0, bs1 /*unused*/, g_c1, g_h1[p ^ 1], b0, bq, jj, ju);
        p ^= 1;
    }

    gbar(gen);
    if (sl == 0) head_dot(g_h1[p], fc_w, fc_b, out, 0, b0, tid);

    // ---------------- autoregressive prediction ----------------
    for (int s = 1; s < FUT; s++) {
        gbar(gen);
        // pred layer 0
        zero_c(cfr);
        gemm16(cfr, g_h0[p] + (size_t)b0 * HID, g_wh[3], u0, shA, shB, tid, aAddr0, bAddr0);
        dump_c(cfr, shC, wm, wn, gid, tid4);
        __syncthreads();
        {
            float xin[4];
#pragma unroll
            for (int i = 0; i < 4; i++)
                xin[i] = __ldcg(&g_o[b0 + bq * 4 + i]);
            cell_update(shC, pbs0, xin, pwi0, g_c0, g_h0[p ^ 1], b0, bq, jj, ju);
        }
        gbar(gen);
        // pred layer 1
        zero_c(cfr);
        gemm16(cfr, g_h0[p ^ 1] + (size_t)b0 * HID, g_wh[4], u0, shA, shB, tid, aAddr0, bAddr0);
        gemm16(cfr, g_h1[p]     + (size_t)b0 * HID, g_wh[5], u0, shA, shB, tid, aAddr0, bAddr0);
        dump_c(cfr, shC, wm, wn, gid, tid4);
        __syncthreads();
        cell_update(shC, pbs1, (const float*)0, pbs1 /*unused*/, g_c1, g_h1[p ^ 1], b0, bq, jj, ju);
        gbar(gen);
        if (sl == 0) head_dot(g_h1[p ^ 1], pfc_w, pfc_b, out, s, b0, tid);
        p ^= 1;
    }
}

// ---------------- launch ----------------
extern "C" void kernel_launch(void* const* d_in, const int* in_sizes, int n_in,
                              void* d_out, int out_size) {
    (void)in_sizes; (void)n_in; (void)out_size;
    cudaFuncSetAttribute(lstm_kernel, cudaFuncAttributeMaxDynamicSharedMemorySize, SMEM_BYTES);

    const float* x      = (const float*)d_in[0];
    // d_in[1] = future (scalar) — fixed shapes, FUT hardcoded
    const float* w_ih0  = (const float*)d_in[2];
    const float* w_hh0  = (const float*)d_in[3];
    const float* b_ih0  = (const float*)d_in[4];
    const float* b_hh0  = (const float*)d_in[5];
    const float* w_ih1  = (const float*)d_in[6];
    const float* w_hh1  = (const float*)d_in[7];
    const float* b_ih1  = (const float*)d_in[8];
    const float* b_hh1  = (const float*)d_in[9];
    const float* fc_w   = (const float*)d_in[10];
    const float* fc_b   = (const float*)d_in[11];
    const float* pw_ih0 = (const float*)d_in[12];
    const float* pw_hh0 = (const float*)d_in[13];
    const float* pb_ih0 = (const float*)d_in[14];
    const float* pb_hh0 = (const float*)d_in[15];
    const float* pw_ih1 = (const float*)d_in[16];
    const float* pw_hh1 = (const float*)d_in[17];
    const float* pb_ih1 = (const float*)d_in[18];
    const float* pb_hh1 = (const float*)d_in[19];
    const float* pfc_w  = (const float*)d_in[20];
    const float* pfc_b  = (const float*)d_in[21];

    // fp16 weight conversion + state zero + barrier reset
    init_kernel<<<1024, 256>>>(w_hh0, w_ih1, w_hh1, pw_hh0, pw_ih1, pw_hh1);

    lstm_kernel<<<NCTA, NTHR, SMEM_BYTES>>>(
        x, w_ih0, b_ih0, b_hh0, b_ih1, b_hh1, fc_w, fc_b,
        pw_ih0, pb_ih0, pb_hh0, pb_ih1, pb_hh1, pfc_w, pfc_b, (float*)d_out);
}